// round 8
// baseline (speedup 1.0000x reference)
#include <cuda_runtime.h>
#include <cuda_bf16.h>
#include <cstdint>

#define B_ROWS 32768
#define C_COLS 1000
#define C_PAD  1024
#define FDIM   256

#define TM   32                // rows per CTA (cos tile fully register-resident)
#define TNC  128               // N-chunk width
#define NCHUNKS (C_PAD / TNC)  // 8
#define THREADS 512            // 16 warps

#define APAD   264             // 256 + 8 bf16 pad -> conflict-free ldmatrix
#define ROWB   (APAD * 2)      // 528 B per smem row
#define A_BYTES (TM * ROWB)    // 16896
#define B_BUF   (TNC * ROWB)   // 67584 per buffer
#define RS_OFF  (A_BYTES + 2 * B_BUF)    // 152064
#define SMEM_TOTAL (RS_OFF + TM * 4)     // 152192 (1 CTA/SM)

// ---- scratch (device global; no runtime allocation) ------------------------
__device__ __nv_bfloat16 g_pb[C_PAD * FDIM];   // normalized prototypes, bf16 (zero-padded)

// ---- helpers ----------------------------------------------------------------
__device__ __forceinline__ uint32_t smem_u32(const void* p) {
    uint32_t a;
    asm("{ .reg .u64 t; cvta.to.shared.u64 t, %1; cvt.u32.u64 %0, t; }" : "=r"(a) : "l"(p));
    return a;
}
__device__ __forceinline__ void ldsm4(uint32_t* r, uint32_t addr) {
    asm volatile("ldmatrix.sync.aligned.m8n8.x4.shared.b16 {%0,%1,%2,%3}, [%4];"
                 : "=r"(r[0]), "=r"(r[1]), "=r"(r[2]), "=r"(r[3]) : "r"(addr));
}
__device__ __forceinline__ void ldsm2(uint32_t* r, uint32_t addr) {
    asm volatile("ldmatrix.sync.aligned.m8n8.x2.shared.b16 {%0,%1}, [%2];"
                 : "=r"(r[0]), "=r"(r[1]) : "r"(addr));
}
__device__ __forceinline__ void mma16816(float* c, const uint32_t* a, uint32_t b0, uint32_t b1) {
    asm volatile(
        "mma.sync.aligned.m16n8k16.row.col.f32.bf16.bf16.f32 "
        "{%0,%1,%2,%3}, {%4,%5,%6,%7}, {%8,%9}, {%0,%1,%2,%3};"
        : "+f"(c[0]), "+f"(c[1]), "+f"(c[2]), "+f"(c[3])
        : "r"(a[0]), "r"(a[1]), "r"(a[2]), "r"(a[3]), "r"(b0), "r"(b1));
}
__device__ __forceinline__ void cp_async16(uint32_t smem_dst, const void* gptr) {
    asm volatile("cp.async.cg.shared.global [%0], [%1], 16;"
                 :: "r"(smem_dst), "l"(gptr) : "memory");
}
__device__ __forceinline__ void cp_commit() {
    asm volatile("cp.async.commit_group;" ::: "memory");
}
__device__ __forceinline__ void cp_wait1() {
    asm volatile("cp.async.wait_group 1;" ::: "memory");
}

// ---------------------------------------------------------------------------
// Prototype normalize + bf16 convert (1024 padded rows, zero tail).
// ---------------------------------------------------------------------------
__global__ void __launch_bounds__(256) conv_proto_kernel(const float* __restrict__ x) {
    int gw   = (blockIdx.x * blockDim.x + threadIdx.x) >> 5;
    int lane = threadIdx.x & 31;
    if (gw >= C_PAD) return;
    uint4 o4 = {0u, 0u, 0u, 0u};
    if (gw < C_COLS) {
        const float4* r4 = reinterpret_cast<const float4*>(x + (size_t)gw * FDIM);
        float4 a = r4[lane * 2], b = r4[lane * 2 + 1];
        float s = a.x*a.x + a.y*a.y + a.z*a.z + a.w*a.w + b.x*b.x + b.y*b.y + b.z*b.z + b.w*b.w;
#pragma unroll
        for (int o = 16; o; o >>= 1) s += __shfl_xor_sync(0xffffffffu, s, o);
        float inv = 1.0f / fmaxf(sqrtf(s), 1e-12f);
        __nv_bfloat162 p0 = __floats2bfloat162_rn(a.x*inv, a.y*inv);
        __nv_bfloat162 p1 = __floats2bfloat162_rn(a.z*inv, a.w*inv);
        __nv_bfloat162 p2 = __floats2bfloat162_rn(b.x*inv, b.y*inv);
        __nv_bfloat162 p3 = __floats2bfloat162_rn(b.z*inv, b.w*inv);
        o4.x = *reinterpret_cast<uint32_t*>(&p0); o4.y = *reinterpret_cast<uint32_t*>(&p1);
        o4.z = *reinterpret_cast<uint32_t*>(&p2); o4.w = *reinterpret_cast<uint32_t*>(&p3);
    }
    reinterpret_cast<uint4*>(g_pb)[(size_t)gw * 32 + lane] = o4;
}

// ---------------------------------------------------------------------------
// Fused single-pass: normalize A -> HMMA GEMM with register-resident 32x1024
// cos tile -> iso in regs -> rowmean -> final logits stored once.
// 16 warps; each owns an 8-col slice per 128-col chunk (warp tile 32x8).
// ---------------------------------------------------------------------------
__global__ void __launch_bounds__(THREADS, 1) fused_kernel(
    const float* __restrict__ feats,
    const float* __restrict__ dscale,
    const float* __restrict__ temp,
    float* __restrict__ out)
{
    extern __shared__ char smem[];
    char*  smA = smem;
    char*  smB = smem + A_BYTES;
    float* rs  = reinterpret_cast<float*>(smem + RS_OFF);

    const uint32_t sbA  = smem_u32(smA);
    const uint32_t sbB  = smem_u32(smB);

    const int tid  = threadIdx.x;
    const int wid  = tid >> 5;         // 0..15
    const int lane = tid & 31;
    const int q    = lane >> 2;        // fragment row-within-8
    const int row0 = blockIdx.x * TM;

    if (tid < TM) rs[tid] = 0.0f;

    // ---- B chunk loader: 128 rows x 32 16B-chunks = 8 cp.async per thread ----
    const char* pbB = reinterpret_cast<const char*>(g_pb);
    auto load_chunk = [&](int nc, int buf) {
#pragma unroll
        for (int i = 0; i < 8; i++) {
            int idx = tid + i * THREADS;
            int r = idx >> 5, kc = idx & 31;
            cp_async16(sbB + buf * B_BUF + r * ROWB + kc * 16,
                       pbB + ((size_t)(nc * TNC + r) * FDIM + kc * 8) * 2);
        }
        cp_commit();
    };

    // prologue: prefetch chunks 0 and 1 (overlaps with A normalize below)
    load_chunk(0, 0);
    load_chunk(1, 1);

    // ---- A tile: load fp32, normalize, convert, store bf16 (warp per row) ----
    const float4* f4 = reinterpret_cast<const float4*>(feats);
#pragma unroll
    for (int rr = 0; rr < TM / 16; rr++) {
        int r = wid + rr * 16;
        float4 a = f4[(size_t)(row0 + r) * 64 + lane * 2];
        float4 b = f4[(size_t)(row0 + r) * 64 + lane * 2 + 1];
        float sn = a.x*a.x + a.y*a.y + a.z*a.z + a.w*a.w + b.x*b.x + b.y*b.y + b.z*b.z + b.w*b.w;
#pragma unroll
        for (int o = 16; o; o >>= 1) sn += __shfl_xor_sync(0xffffffffu, sn, o);
        float inv = 1.0f / fmaxf(sqrtf(sn), 1e-12f);
        __nv_bfloat162 p0 = __floats2bfloat162_rn(a.x*inv, a.y*inv);
        __nv_bfloat162 p1 = __floats2bfloat162_rn(a.z*inv, a.w*inv);
        __nv_bfloat162 p2 = __floats2bfloat162_rn(b.x*inv, b.y*inv);
        __nv_bfloat162 p3 = __floats2bfloat162_rn(b.z*inv, b.w*inv);
        uint4 o4;
        o4.x = *reinterpret_cast<uint32_t*>(&p0); o4.y = *reinterpret_cast<uint32_t*>(&p1);
        o4.z = *reinterpret_cast<uint32_t*>(&p2); o4.w = *reinterpret_cast<uint32_t*>(&p3);
        *reinterpret_cast<uint4*>(smA + r * ROWB + lane * 16) = o4;
    }

    // A fragments: warp-uniform (broadcast across 16 warps)
    const uint32_t aBase = sbA + (uint32_t)((lane & 15) * APAD + ((lane >> 4) << 3)) * 2;
    // B fragments: ldmatrix.x2, lanes 0-7 -> cols wid*8+0..7 @k0, lanes 8-15 @k8
    const uint32_t bOff  = (uint32_t)((wid * 8 + (lane & 7)) * APAD + ((lane >> 3) & 1) * 8) * 2;

    // ---- persistent cos accumulators: 8 chunks x 2 m-frags x 4 = 64 regs ----
    float acc[NCHUNKS][2][4];
#pragma unroll
    for (int nc = 0; nc < NCHUNKS; nc++)
#pragma unroll
        for (int i = 0; i < 2; i++)
#pragma unroll
            for (int c = 0; c < 4; c++) acc[nc][i][c] = 0.0f;

#pragma unroll
    for (int nc = 0; nc < NCHUNKS; nc++) {
        cp_wait1();
        __syncthreads();     // chunk nc visible (also orders A tile on nc==0)

        const uint32_t bBase = sbB + (nc & 1) * B_BUF + bOff;

#pragma unroll
        for (int k0 = 0; k0 < FDIM; k0 += 16) {
            uint32_t a0[4], a1[4], b[2];
            ldsm4(a0, aBase + k0 * 2);
            ldsm4(a1, aBase + 16 * ROWB + k0 * 2);
            ldsm2(b,  bBase + k0 * 2);
            mma16816(acc[nc][0], a0, b[0], b[1]);
            mma16816(acc[nc][1], a1, b[0], b[1]);
        }
        __syncthreads();     // buffer reads done before refill

        if (nc + 2 < NCHUNKS) load_chunk(nc + 2, nc & 1);
        else                  cp_commit();     // keep group count invariant
    }

    // ---- iso in place + per-row partial sums ----
    const float s = fabsf(__ldg(dscale));
    float rsum[4] = {0.f, 0.f, 0.f, 0.f};
#pragma unroll
    for (int nc = 0; nc < NCHUNKS; nc++) {
        int col = nc * TNC + wid * 8 + (lane & 3) * 2;
#pragma unroll
        for (int i = 0; i < 2; i++) {
            if (col < C_COLS) {
                float* a = acc[nc][i];
                a[0] = s * sqrtf(fmaxf(1.0f - a[0], 0.0f));
                a[1] = s * sqrtf(fmaxf(1.0f - a[1], 0.0f));
                a[2] = s * sqrtf(fmaxf(1.0f - a[2], 0.0f));
                a[3] = s * sqrtf(fmaxf(1.0f - a[3], 0.0f));
                rsum[2 * i]     += a[0] + a[1];
                rsum[2 * i + 1] += a[2] + a[3];
            }
        }
    }

    // reduce over the 4 lanes sharing each row, then 16 warps via smem atomics
#pragma unroll
    for (int k = 0; k < 4; k++) {
        float v = rsum[k];
        v += __shfl_xor_sync(0xffffffffu, v, 1);
        v += __shfl_xor_sync(0xffffffffu, v, 2);
        if ((lane & 3) == 0) {
            int rloc = 16 * (k >> 1) + 8 * (k & 1) + q;
            atomicAdd(&rs[rloc], v);
        }
    }
    __syncthreads();

    // ---- final store: logits = -(iso + mean)/T, straight from registers ----
    const float itT = 1.0f / __ldg(temp);
    float mean[4];
#pragma unroll
    for (int k = 0; k < 4; k++)
        mean[k] = rs[16 * (k >> 1) + 8 * (k & 1) + q] * (1.0f / (float)C_COLS);

#pragma unroll
    for (int nc = 0; nc < NCHUNKS; nc++) {
        int col = nc * TNC + wid * 8 + (lane & 3) * 2;
#pragma unroll
        for (int i = 0; i < 2; i++) {
            if (col < C_COLS) {
                int r0 = row0 + 16 * i + q;
                const float* a = acc[nc][i];
                float2 v0 = make_float2(-(a[0] + mean[2*i])     * itT,
                                        -(a[1] + mean[2*i])     * itT);
                float2 v1 = make_float2(-(a[2] + mean[2*i + 1]) * itT,
                                        -(a[3] + mean[2*i + 1]) * itT);
                *reinterpret_cast<float2*>(&out[(size_t)r0 * C_COLS + col])       = v0;
                *reinterpret_cast<float2*>(&out[(size_t)(r0 + 8) * C_COLS + col]) = v1;
            }
        }
    }
}

// ---------------------------------------------------------------------------
extern "C" void kernel_launch(void* const* d_in, const int* in_sizes, int n_in,
                              void* d_out, int out_size)
{
    const float* feats  = (const float*)d_in[0];
    const float* protos = (const float*)d_in[1];
    const float* ds     = (const float*)d_in[2];
    const float* temp   = (const float*)d_in[3];
    float* out = (float*)d_out;

    cudaFuncSetAttribute(fused_kernel,
                         cudaFuncAttributeMaxDynamicSharedMemorySize, SMEM_TOTAL);

    conv_proto_kernel<<<C_PAD / 8, 256>>>(protos);
    fused_kernel<<<B_ROWS / TM, THREADS, SMEM_TOTAL>>>(feats, ds, temp, out);
}

// round 10
// speedup vs baseline: 1.2494x; 1.2494x over previous
#include <cuda_runtime.h>
#include <cuda_bf16.h>
#include <cstdint>

#define B_ROWS 32768
#define C_COLS 1000
#define C_PAD  1024
#define FDIM   256

#define TM   32                // rows per CTA (cos tile fully register-resident)
#define KSL  32                // K-slice width
#define NKSL (FDIM / KSL)      // 8
#define THREADS 512            // 16 warps, each owns 64 cols (8 n-blocks of 8)

#define APAD   264             // A: 256 + 8 bf16 pad -> conflict-free ldmatrix
#define ROWB   (APAD * 2)      // 528 B per A smem row (33*16: aligned)
#define A_BYTES (TM * ROWB)    // 16896
#define BROW   80              // B slice row: 64B data + 16B pad (5*16: aligned, odd phase)
#define B_SLICE (C_PAD * BROW) // 81920 per buffer
#define RS_OFF  (A_BYTES + 2 * B_SLICE)  // 180736
#define SMEM_TOTAL (RS_OFF + TM * 4)     // 180864 (1 CTA/SM)

// ---- scratch (device global; no runtime allocation) ------------------------
__device__ __nv_bfloat16 g_pb[C_PAD * FDIM];   // normalized prototypes, bf16 (zero-padded)

// ---- helpers ----------------------------------------------------------------
__device__ __forceinline__ uint32_t smem_u32(const void* p) {
    uint32_t a;
    asm("{ .reg .u64 t; cvta.to.shared.u64 t, %1; cvt.u32.u64 %0, t; }" : "=r"(a) : "l"(p));
    return a;
}
__device__ __forceinline__ void ldsm4(uint32_t* r, uint32_t addr) {
    asm volatile("ldmatrix.sync.aligned.m8n8.x4.shared.b16 {%0,%1,%2,%3}, [%4];"
                 : "=r"(r[0]), "=r"(r[1]), "=r"(r[2]), "=r"(r[3]) : "r"(addr));
}
__device__ __forceinline__ void mma16816(float* c, const uint32_t* a, uint32_t b0, uint32_t b1) {
    asm volatile(
        "mma.sync.aligned.m16n8k16.row.col.f32.bf16.bf16.f32 "
        "{%0,%1,%2,%3}, {%4,%5,%6,%7}, {%8,%9}, {%0,%1,%2,%3};"
        : "+f"(c[0]), "+f"(c[1]), "+f"(c[2]), "+f"(c[3])
        : "r"(a[0]), "r"(a[1]), "r"(a[2]), "r"(a[3]), "r"(b0), "r"(b1));
}
__device__ __forceinline__ void cp_async16(uint32_t smem_dst, const void* gptr) {
    asm volatile("cp.async.cg.shared.global [%0], [%1], 16;"
                 :: "r"(smem_dst), "l"(gptr) : "memory");
}
__device__ __forceinline__ void cp_commit() {
    asm volatile("cp.async.commit_group;" ::: "memory");
}
__device__ __forceinline__ void cp_wait1() {
    asm volatile("cp.async.wait_group 1;" ::: "memory");
}

// ---------------------------------------------------------------------------
// Prototype normalize + bf16 convert (1024 padded rows, zero tail).
// ---------------------------------------------------------------------------
__global__ void __launch_bounds__(256) conv_proto_kernel(const float* __restrict__ x) {
    int gw   = (blockIdx.x * blockDim.x + threadIdx.x) >> 5;
    int lane = threadIdx.x & 31;
    if (gw >= C_PAD) return;
    uint4 o4 = {0u, 0u, 0u, 0u};
    if (gw < C_COLS) {
        const float4* r4 = reinterpret_cast<const float4*>(x + (size_t)gw * FDIM);
        float4 a = r4[lane * 2], b = r4[lane * 2 + 1];
        float s = a.x*a.x + a.y*a.y + a.z*a.z + a.w*a.w + b.x*b.x + b.y*b.y + b.z*b.z + b.w*b.w;
#pragma unroll
        for (int o = 16; o; o >>= 1) s += __shfl_xor_sync(0xffffffffu, s, o);
        float inv = 1.0f / fmaxf(sqrtf(s), 1e-12f);
        __nv_bfloat162 p0 = __floats2bfloat162_rn(a.x*inv, a.y*inv);
        __nv_bfloat162 p1 = __floats2bfloat162_rn(a.z*inv, a.w*inv);
        __nv_bfloat162 p2 = __floats2bfloat162_rn(b.x*inv, b.y*inv);
        __nv_bfloat162 p3 = __floats2bfloat162_rn(b.z*inv, b.w*inv);
        o4.x = *reinterpret_cast<uint32_t*>(&p0); o4.y = *reinterpret_cast<uint32_t*>(&p1);
        o4.z = *reinterpret_cast<uint32_t*>(&p2); o4.w = *reinterpret_cast<uint32_t*>(&p3);
    }
    reinterpret_cast<uint4*>(g_pb)[(size_t)gw * 32 + lane] = o4;
}

// ---------------------------------------------------------------------------
// Fused single-pass, K-sliced: normalize A -> HMMA GEMM (B staged as k-slices
// of all 1024 cols; A fragments loaded once per slice and reused across 8
// n-blocks) -> iso in regs -> rowmean -> final logits stored once.
// 16 warps; warp owns 32 rows x 64 cols (8 n-blocks of 8 cols).
// ---------------------------------------------------------------------------
__global__ void __launch_bounds__(THREADS, 1) fused_kernel(
    const float* __restrict__ feats,
    const float* __restrict__ dscale,
    const float* __restrict__ temp,
    float* __restrict__ out)
{
    extern __shared__ char smem[];
    char*  smA = smem;
    float* rs  = reinterpret_cast<float*>(smem + RS_OFF);

    const uint32_t sbA  = smem_u32(smA);
    const uint32_t sbB  = sbA + A_BYTES;

    const int tid  = threadIdx.x;
    const int wid  = tid >> 5;         // 0..15
    const int lane = tid & 31;
    const int q    = lane >> 2;        // fragment row-within-8
    const int row0 = blockIdx.x * TM;

    if (tid < TM) rs[tid] = 0.0f;

    // ---- B k-slice loader: 1024 cols x 4 16B-chunks = 8 cp.async per thread ----
    const char* pbB = reinterpret_cast<const char*>(g_pb);
    auto load_slice = [&](int ks, int buf) {
#pragma unroll
        for (int i = 0; i < 8; i++) {
            int idx = tid + i * THREADS;        // 0..4095
            int col = idx >> 2, ck = idx & 3;
            cp_async16(sbB + buf * B_SLICE + col * BROW + ck * 16,
                       pbB + ((size_t)col * FDIM + ks * KSL + ck * 8) * 2);
        }
        cp_commit();
    };

    // prologue: prefetch slices 0 and 1 (overlaps with A normalize below)
    load_slice(0, 0);
    load_slice(1, 1);

    // ---- A tile: load fp32, normalize, convert, store bf16 (warp per row) ----
    const float4* f4 = reinterpret_cast<const float4*>(feats);
#pragma unroll
    for (int rr = 0; rr < TM / 16; rr++) {
        int r = wid + rr * 16;
        float4 a = f4[(size_t)(row0 + r) * 64 + lane * 2];
        float4 b = f4[(size_t)(row0 + r) * 64 + lane * 2 + 1];
        float sn = a.x*a.x + a.y*a.y + a.z*a.z + a.w*a.w + b.x*b.x + b.y*b.y + b.z*b.z + b.w*b.w;
#pragma unroll
        for (int o = 16; o; o >>= 1) sn += __shfl_xor_sync(0xffffffffu, sn, o);
        float inv = 1.0f / fmaxf(sqrtf(sn), 1e-12f);
        __nv_bfloat162 p0 = __floats2bfloat162_rn(a.x*inv, a.y*inv);
        __nv_bfloat162 p1 = __floats2bfloat162_rn(a.z*inv, a.w*inv);
        __nv_bfloat162 p2 = __floats2bfloat162_rn(b.x*inv, b.y*inv);
        __nv_bfloat162 p3 = __floats2bfloat162_rn(b.z*inv, b.w*inv);
        uint4 o4;
        o4.x = *reinterpret_cast<uint32_t*>(&p0); o4.y = *reinterpret_cast<uint32_t*>(&p1);
        o4.z = *reinterpret_cast<uint32_t*>(&p2); o4.w = *reinterpret_cast<uint32_t*>(&p3);
        *reinterpret_cast<uint4*>(smA + r * ROWB + lane * 16) = o4;
    }

    // A fragment base (warp-uniform broadcast; loaded once per k-slice)
    const uint32_t aBase = sbA + (uint32_t)((lane & 15) * APAD + ((lane >> 4) << 3)) * 2;
    // B fragment base: ldsm4 over 8 cols x 32 k: lane group g=lane>>3 -> k byte-off g*16
    const uint32_t bOff  = (uint32_t)((wid * 64 + (lane & 7)) * BROW + (lane >> 3) * 16);

    // ---- persistent cos accumulators: 8 n-blocks x 2 m-frags x 4 = 64 regs ----
    float acc[8][2][4];
#pragma unroll
    for (int j = 0; j < 8; j++)
#pragma unroll
        for (int i = 0; i < 2; i++)
#pragma unroll
            for (int c = 0; c < 4; c++) acc[j][i][c] = 0.0f;

#pragma unroll
    for (int ks = 0; ks < NKSL; ks++) {
        cp_wait1();
        __syncthreads();     // slice ks visible (also orders A tile on ks==0)

        // A fragments for this k-slice: [m2][k2], reused across 8 n-blocks
        uint32_t A00[4], A01[4], A10[4], A11[4];
        ldsm4(A00, aBase + (ks * KSL) * 2);
        ldsm4(A01, aBase + (ks * KSL + 16) * 2);
        ldsm4(A10, aBase + 16 * ROWB + (ks * KSL) * 2);
        ldsm4(A11, aBase + 16 * ROWB + (ks * KSL + 16) * 2);

        const uint32_t bBase = sbB + (ks & 1) * B_SLICE + bOff;

#pragma unroll
        for (int j = 0; j < 8; j++) {
            uint32_t b[4];                      // k0-7, k8-15, k16-23, k24-31
            ldsm4(b, bBase + j * 8 * BROW);
            mma16816(acc[j][0], A00, b[0], b[1]);
            mma16816(acc[j][1], A10, b[0], b[1]);
            mma16816(acc[j][0], A01, b[2], b[3]);
            mma16816(acc[j][1], A11, b[2], b[3]);
        }
        __syncthreads();     // slice reads done before refill

        if (ks + 2 < NKSL) load_slice(ks + 2, ks & 1);
        else               cp_commit();        // keep group count invariant
    }

    // ---- iso in place + per-row partial sums ----
    const float s = fabsf(__ldg(dscale));
    float rsum[4] = {0.f, 0.f, 0.f, 0.f};
#pragma unroll
    for (int j = 0; j < 8; j++) {
        int col = wid * 64 + j * 8 + (lane & 3) * 2;
#pragma unroll
        for (int i = 0; i < 2; i++) {
            if (col < C_COLS) {
                float* a = acc[j][i];
                a[0] = s * sqrtf(fmaxf(1.0f - a[0], 0.0f));
                a[1] = s * sqrtf(fmaxf(1.0f - a[1], 0.0f));
                a[2] = s * sqrtf(fmaxf(1.0f - a[2], 0.0f));
                a[3] = s * sqrtf(fmaxf(1.0f - a[3], 0.0f));
                rsum[2 * i]     += a[0] + a[1];
                rsum[2 * i + 1] += a[2] + a[3];
            }
        }
    }

    // reduce over the 4 lanes sharing each row, then 16 warps via smem atomics
#pragma unroll
    for (int k = 0; k < 4; k++) {
        float v = rsum[k];
        v += __shfl_xor_sync(0xffffffffu, v, 1);
        v += __shfl_xor_sync(0xffffffffu, v, 2);
        if ((lane & 3) == 0) {
            int rloc = 16 * (k >> 1) + 8 * (k & 1) + q;
            atomicAdd(&rs[rloc], v);
        }
    }
    __syncthreads();

    // ---- final store: logits = -(iso + mean)/T, straight from registers ----
    const float itT = 1.0f / __ldg(temp);
    float mean[4];
#pragma unroll
    for (int k = 0; k < 4; k++)
        mean[k] = rs[16 * (k >> 1) + 8 * (k & 1) + q] * (1.0f / (float)C_COLS);

#pragma unroll
    for (int j = 0; j < 8; j++) {
        int col = wid * 64 + j * 8 + (lane & 3) * 2;
#pragma unroll
        for (int i = 0; i < 2; i++) {
            if (col < C_COLS) {
                int r0 = row0 + 16 * i + q;
                const float* a = acc[j][i];
                float2 v0 = make_float2(-(a[0] + mean[2*i])     * itT,
                                        -(a[1] + mean[2*i])     * itT);
                float2 v1 = make_float2(-(a[2] + mean[2*i + 1]) * itT,
                                        -(a[3] + mean[2*i + 1]) * itT);
                *reinterpret_cast<float2*>(&out[(size_t)r0 * C_COLS + col])       = v0;
                *reinterpret_cast<float2*>(&out[(size_t)(r0 + 8) * C_COLS + col]) = v1;
            }
        }
    }
}

// ---------------------------------------------------------------------------
extern "C" void kernel_launch(void* const* d_in, const int* in_sizes, int n_in,
                              void* d_out, int out_size)
{
    const float* feats  = (const float*)d_in[0];
    const float* protos = (const float*)d_in[1];
    const float* ds     = (const float*)d_in[2];
    const float* temp   = (const float*)d_in[3];
    float* out = (float*)d_out;

    cudaFuncSetAttribute(fused_kernel,
                         cudaFuncAttributeMaxDynamicSharedMemorySize, SMEM_TOTAL);

    conv_proto_kernel<<<C_PAD / 8, 256>>>(protos);
    fused_kernel<<<B_ROWS / TM, THREADS, SMEM_TOTAL>>>(feats, ds, temp, out);
}

// round 11
// speedup vs baseline: 1.3914x; 1.1137x over previous
#include <cuda_runtime.h>
#include <cuda_bf16.h>
#include <cstdint>

#define B_ROWS 32768
#define C_COLS 1000
#define C_PAD  1024
#define FDIM   256

#define TM   32                // rows per CTA (cos tile fully register-resident)
#define KSL  32                // K-slice width
#define NKSL (FDIM / KSL)      // 8
#define THREADS 512            // 16 warps, each owns 64 cols (8 n-blocks of 8)

#define APAD   264             // A: 256 + 8 bf16 pad -> conflict-free ldmatrix
#define ROWB   (APAD * 2)      // 528 B per A smem row (33*16: aligned)
#define A_BYTES (TM * ROWB)    // 16896
#define BROW   80              // B slice row: 64B data + 16B pad (5*16: aligned, conflict-free)
#define B_SLICE (C_PAD * BROW) // 81920 per buffer
#define RS_OFF  (A_BYTES + 2 * B_SLICE)  // 180736
#define SMEM_TOTAL (RS_OFF + TM * 4)     // 180864 (1 CTA/SM)

// ---- scratch (device global; no runtime allocation) ------------------------
__device__ __nv_bfloat16 g_pb[C_PAD * FDIM];   // normalized prototypes, bf16 (zero-padded)

// ---- helpers ----------------------------------------------------------------
__device__ __forceinline__ uint32_t smem_u32(const void* p) {
    uint32_t a;
    asm("{ .reg .u64 t; cvta.to.shared.u64 t, %1; cvt.u32.u64 %0, t; }" : "=r"(a) : "l"(p));
    return a;
}
__device__ __forceinline__ void ldsm4(uint32_t* r, uint32_t addr) {
    asm volatile("ldmatrix.sync.aligned.m8n8.x4.shared.b16 {%0,%1,%2,%3}, [%4];"
                 : "=r"(r[0]), "=r"(r[1]), "=r"(r[2]), "=r"(r[3]) : "r"(addr));
}
__device__ __forceinline__ void mma16816(float* c, const uint32_t* a, uint32_t b0, uint32_t b1) {
    asm volatile(
        "mma.sync.aligned.m16n8k16.row.col.f32.bf16.bf16.f32 "
        "{%0,%1,%2,%3}, {%4,%5,%6,%7}, {%8,%9}, {%0,%1,%2,%3};"
        : "+f"(c[0]), "+f"(c[1]), "+f"(c[2]), "+f"(c[3])
        : "r"(a[0]), "r"(a[1]), "r"(a[2]), "r"(a[3]), "r"(b0), "r"(b1));
}
__device__ __forceinline__ void cp_async16(uint32_t smem_dst, const void* gptr) {
    asm volatile("cp.async.cg.shared.global [%0], [%1], 16;"
                 :: "r"(smem_dst), "l"(gptr) : "memory");
}
__device__ __forceinline__ void cp_commit() {
    asm volatile("cp.async.commit_group;" ::: "memory");
}
__device__ __forceinline__ void cp_wait1() {
    asm volatile("cp.async.wait_group 1;" ::: "memory");
}

// ---------------------------------------------------------------------------
// Prototype normalize + bf16 convert (1024 padded rows, zero tail).
// ---------------------------------------------------------------------------
__global__ void __launch_bounds__(256) conv_proto_kernel(const float* __restrict__ x) {
    int gw   = (blockIdx.x * blockDim.x + threadIdx.x) >> 5;
    int lane = threadIdx.x & 31;
    if (gw >= C_PAD) return;
    uint4 o4 = {0u, 0u, 0u, 0u};
    if (gw < C_COLS) {
        const float4* r4 = reinterpret_cast<const float4*>(x + (size_t)gw * FDIM);
        float4 a = r4[lane * 2], b = r4[lane * 2 + 1];
        float s = a.x*a.x + a.y*a.y + a.z*a.z + a.w*a.w + b.x*b.x + b.y*b.y + b.z*b.z + b.w*b.w;
#pragma unroll
        for (int o = 16; o; o >>= 1) s += __shfl_xor_sync(0xffffffffu, s, o);
        float inv = 1.0f / fmaxf(sqrtf(s), 1e-12f);
        __nv_bfloat162 p0 = __floats2bfloat162_rn(a.x*inv, a.y*inv);
        __nv_bfloat162 p1 = __floats2bfloat162_rn(a.z*inv, a.w*inv);
        __nv_bfloat162 p2 = __floats2bfloat162_rn(b.x*inv, b.y*inv);
        __nv_bfloat162 p3 = __floats2bfloat162_rn(b.z*inv, b.w*inv);
        o4.x = *reinterpret_cast<uint32_t*>(&p0); o4.y = *reinterpret_cast<uint32_t*>(&p1);
        o4.z = *reinterpret_cast<uint32_t*>(&p2); o4.w = *reinterpret_cast<uint32_t*>(&p3);
    }
    reinterpret_cast<uint4*>(g_pb)[(size_t)gw * 32 + lane] = o4;
}

// ---------------------------------------------------------------------------
// Fused single-pass, K-sliced, warp-autonomous pipelines:
// each warp cp.asyncs ONLY its own 64 B-columns and syncs with
// wait_group+syncwarp -> no CTA barriers in the mainloop.
// ---------------------------------------------------------------------------
__global__ void __launch_bounds__(THREADS, 1) fused_kernel(
    const float* __restrict__ feats,
    const float* __restrict__ dscale,
    const float* __restrict__ temp,
    float* __restrict__ out)
{
    extern __shared__ char smem[];
    char*  smA = smem;
    float* rs  = reinterpret_cast<float*>(smem + RS_OFF);

    const uint32_t sbA  = smem_u32(smA);
    const uint32_t sbB  = sbA + A_BYTES;

    const int tid  = threadIdx.x;
    const int wid  = tid >> 5;         // 0..15
    const int lane = tid & 31;
    const int q    = lane >> 2;        // fragment row-within-8
    const int row0 = blockIdx.x * TM;

    if (tid < TM) rs[tid] = 0.0f;

    // ---- per-warp B k-slice loader: warp's 64 cols x 64B = 4KB/slice.
    // lane l -> col (i*8 + (l>>2)), chunk (l&3); 8 iterations of 32 lanes.
    const char* pbB = reinterpret_cast<const char*>(g_pb);
    const int  colL = wid * 64 + (lane >> 2);    // lane's column within slice
    const int  ckL  = lane & 3;                  // lane's 16B chunk (of 4)
    auto load_slice = [&](int ks, int buf) {
#pragma unroll
        for (int i = 0; i < 8; i++) {
            int col = colL + i * 8;
            cp_async16(sbB + buf * B_SLICE + col * BROW + ckL * 16,
                       pbB + ((size_t)col * FDIM + ks * KSL + ckL * 8) * 2);
        }
        cp_commit();
    };

    // prologue: prefetch this warp's part of slices 0 and 1
    load_slice(0, 0);
    load_slice(1, 1);

    // ---- A tile: load fp32, normalize, convert, store bf16 (warp per row) ----
    const float4* f4 = reinterpret_cast<const float4*>(feats);
#pragma unroll
    for (int rr = 0; rr < TM / 16; rr++) {
        int r = wid + rr * 16;
        float4 a = f4[(size_t)(row0 + r) * 64 + lane * 2];
        float4 b = f4[(size_t)(row0 + r) * 64 + lane * 2 + 1];
        float sn = a.x*a.x + a.y*a.y + a.z*a.z + a.w*a.w + b.x*b.x + b.y*b.y + b.z*b.z + b.w*b.w;
#pragma unroll
        for (int o = 16; o; o >>= 1) sn += __shfl_xor_sync(0xffffffffu, sn, o);
        float inv = 1.0f / fmaxf(sqrtf(sn), 1e-12f);
        __nv_bfloat162 p0 = __floats2bfloat162_rn(a.x*inv, a.y*inv);
        __nv_bfloat162 p1 = __floats2bfloat162_rn(a.z*inv, a.w*inv);
        __nv_bfloat162 p2 = __floats2bfloat162_rn(b.x*inv, b.y*inv);
        __nv_bfloat162 p3 = __floats2bfloat162_rn(b.z*inv, b.w*inv);
        uint4 o4;
        o4.x = *reinterpret_cast<uint32_t*>(&p0); o4.y = *reinterpret_cast<uint32_t*>(&p1);
        o4.z = *reinterpret_cast<uint32_t*>(&p2); o4.w = *reinterpret_cast<uint32_t*>(&p3);
        *reinterpret_cast<uint4*>(smA + r * ROWB + lane * 16) = o4;
    }
    __syncthreads();   // A tile (and rs init) visible to all warps; only CTA sync pre-epilogue

    // A fragment base (warp-uniform broadcast; loaded once per k-slice)
    const uint32_t aBase = sbA + (uint32_t)((lane & 15) * APAD + ((lane >> 4) << 3)) * 2;
    // B fragment base: ldsm4 over 8 cols x 32 k
    const uint32_t bOff  = (uint32_t)((wid * 64 + (lane & 7)) * BROW + (lane >> 3) * 16);

    // ---- persistent cos accumulators: 8 n-blocks x 2 m-frags x 4 = 64 regs ----
    float acc[8][2][4];
#pragma unroll
    for (int j = 0; j < 8; j++)
#pragma unroll
        for (int i = 0; i < 2; i++)
#pragma unroll
            for (int c = 0; c < 4; c++) acc[j][i][c] = 0.0f;

#pragma unroll
    for (int ks = 0; ks < NKSL; ks++) {
        cp_wait1();          // this warp's slice ks landed
        __syncwarp();        // cross-lane visibility within the warp

        // A fragments for this k-slice: [m2][k2], reused across 8 n-blocks
        uint32_t A00[4], A01[4], A10[4], A11[4];
        ldsm4(A00, aBase + (ks * KSL) * 2);
        ldsm4(A01, aBase + (ks * KSL + 16) * 2);
        ldsm4(A10, aBase + 16 * ROWB + (ks * KSL) * 2);
        ldsm4(A11, aBase + 16 * ROWB + (ks * KSL + 16) * 2);

        const uint32_t bBase = sbB + (ks & 1) * B_SLICE + bOff;

#pragma unroll
        for (int j = 0; j < 8; j++) {
            uint32_t b[4];                      // k0-7, k8-15, k16-23, k24-31
            ldsm4(b, bBase + j * 8 * BROW);
            mma16816(acc[j][0], A00, b[0], b[1]);
            mma16816(acc[j][1], A10, b[0], b[1]);
            mma16816(acc[j][0], A01, b[2], b[3]);
            mma16816(acc[j][1], A11, b[2], b[3]);
        }
        // refill this warp's cols (buffer region is warp-private; ldsm reads done)
        if (ks + 2 < NKSL) load_slice(ks + 2, ks & 1);
        else               cp_commit();        // keep group count invariant
    }

    // ---- iso in place + per-row partial sums ----
    const float s = fabsf(__ldg(dscale));
    float rsum[4] = {0.f, 0.f, 0.f, 0.f};
#pragma unroll
    for (int j = 0; j < 8; j++) {
        int col = wid * 64 + j * 8 + (lane & 3) * 2;
#pragma unroll
        for (int i = 0; i < 2; i++) {
            if (col < C_COLS) {
                float* a = acc[j][i];
                a[0] = s * sqrtf(fmaxf(1.0f - a[0], 0.0f));
                a[1] = s * sqrtf(fmaxf(1.0f - a[1], 0.0f));
                a[2] = s * sqrtf(fmaxf(1.0f - a[2], 0.0f));
                a[3] = s * sqrtf(fmaxf(1.0f - a[3], 0.0f));
                rsum[2 * i]     += a[0] + a[1];
                rsum[2 * i + 1] += a[2] + a[3];
            }
        }
    }

    // reduce over the 4 lanes sharing each row, then 16 warps via smem atomics
#pragma unroll
    for (int k = 0; k < 4; k++) {
        float v = rsum[k];
        v += __shfl_xor_sync(0xffffffffu, v, 1);
        v += __shfl_xor_sync(0xffffffffu, v, 2);
        if ((lane & 3) == 0) {
            int rloc = 16 * (k >> 1) + 8 * (k & 1) + q;
            atomicAdd(&rs[rloc], v);
        }
    }
    __syncthreads();

    // ---- final store: logits = -(iso + mean)/T, straight from registers ----
    const float itT = 1.0f / __ldg(temp);
    float mean[4];
#pragma unroll
    for (int k = 0; k < 4; k++)
        mean[k] = rs[16 * (k >> 1) + 8 * (k & 1) + q] * (1.0f / (float)C_COLS);

#pragma unroll
    for (int j = 0; j < 8; j++) {
        int col = wid * 64 + j * 8 + (lane & 3) * 2;
#pragma unroll
        for (int i = 0; i < 2; i++) {
            if (col < C_COLS) {
                int r0 = row0 + 16 * i + q;
                const float* a = acc[j][i];
                float2 v0 = make_float2(-(a[0] + mean[2*i])     * itT,
                                        -(a[1] + mean[2*i])     * itT);
                float2 v1 = make_float2(-(a[2] + mean[2*i + 1]) * itT,
                                        -(a[3] + mean[2*i + 1]) * itT);
                *reinterpret_cast<float2*>(&out[(size_t)r0 * C_COLS + col])       = v0;
                *reinterpret_cast<float2*>(&out[(size_t)(r0 + 8) * C_COLS + col]) = v1;
            }
        }
    }
}

// ---------------------------------------------------------------------------
extern "C" void kernel_launch(void* const* d_in, const int* in_sizes, int n_in,
                              void* d_out, int out_size)
{
    const float* feats  = (const float*)d_in[0];
    const float* protos = (const float*)d_in[1];
    const float* ds     = (const float*)d_in[2];
    const float* temp   = (const float*)d_in[3];
    float* out = (float*)d_out;

    cudaFuncSetAttribute(fused_kernel,
                         cudaFuncAttributeMaxDynamicSharedMemorySize, SMEM_TOTAL);

    conv_proto_kernel<<<C_PAD / 8, 256>>>(protos);
    fused_kernel<<<B_ROWS / TM, THREADS, SMEM_TOTAL>>>(feats, ds, temp, out);
}